// round 11
// baseline (speedup 1.0000x reference)
#include <cuda_runtime.h>

// Demolition_Conv2d: grouped conv (16 groups of 1->32, 3x3, pad 1) + bias,
// per-(cin,cout) 5-bit quant-dequant (scale=15/9), sum over cin.
//
// R11: R10 (cin-pair planes, vertical 4-px slots, NC=4) + latency cover:
//  - prefetch.global.L1 of next cp's 6 tap rows (issued ~1 cp ahead)
//  - occupancy 4 -> 5 blocks/SM (launch_bounds(128,5))

#define CIN   16
#define COUT  32
#define HH    112
#define WW    112
#define NB    8
#define NCP   8      // cin pairs
#define HP    114    // padded height
#define WP    114    // padded width
#define NC    4      // couts per thread
#define NS    4      // vertical pixel slots per thread

typedef unsigned long long f2;

__device__ __align__(16) f2 g_X[NB * NCP * HP * WP];   // ~6.65 MB packed planes

__device__ __forceinline__ f2 pk2(float lo, float hi) {
    f2 r; asm("mov.b64 %0, {%1, %2};" : "=l"(r) : "f"(lo), "f"(hi)); return r;
}
__device__ __forceinline__ void fma2i(f2& acc, f2 a, f2 b) {
    asm("fma.rn.f32x2 %0, %1, %2, %0;" : "+l"(acc) : "l"(a), "l"(b));
}
__device__ __forceinline__ void add2i(f2& acc, f2 b) {
    asm("add.rn.f32x2 %0, %0, %1;" : "+l"(acc) : "l"(b));
}
__device__ __forceinline__ float lanesum(f2 a) {
    float lo, hi;
    asm("mov.b64 {%0, %1}, %2;" : "=f"(lo), "=f"(hi) : "l"(a));
    return lo + hi;
}
__device__ __forceinline__ void pf_l1(const void* p) {
    asm volatile("prefetch.global.L1 [%0];" :: "l"(p));
}

// ---------------- prepass: padded cin-pair planes (2 pairs/thread) --------
#define PPW 57   // wp pairs per row
__global__ __launch_bounds__(256)
void prepass_kernel(const float* __restrict__ x)
{
    int gid = blockIdx.x * 256 + threadIdx.x;    // [0, NB*NCP*HP*PPW)
    if (gid >= NB * NCP * HP * PPW) return;
    int pp = gid % PPW;
    int t  = gid / PPW;
    int hp = t % HP;
    int t2 = t / HP;
    int cp = t2 % NCP;
    int b  = t2 / NCP;

    int h = hp - 1;
    bool rv = (h >= 0) && (h < HH);
    const float* p0 = x + (((b * CIN + 2 * cp)     * HH + h) * WW);
    const float* p1 = x + (((b * CIN + 2 * cp + 1) * HH + h) * WW);

    ulonglong2 outv;
    int w0 = 2 * pp - 1;
    int w1 = 2 * pp;
    bool v0 = rv && (w0 >= 0) && (w0 < WW);
    bool v1 = rv && (w1 >= 0) && (w1 < WW);
    outv.x = v0 ? pk2(p0[w0], p1[w0]) : 0ULL;
    outv.y = v1 ? pk2(p0[w1], p1[w1]) : 0ULL;

    ulonglong2* dst = reinterpret_cast<ulonglong2*>(
        g_X + ((long)((b * NCP + cp) * HP + hp)) * WP) + pp;
    *dst = outv;
}

// ---------------- main kernel ----------------
__global__ __launch_bounds__(128, 5)
void demolition_conv2d_kernel(const float* __restrict__ Wt,
                              const float* __restrict__ bias,
                              float* __restrict__ out)
{
    __shared__ __align__(16) f2 sW[NCP * NC * 10];   // 2560 B

    const float SCALEf = 15.0f / 9.0f;
    const float INVf   = 9.0f / 15.0f;
    const float MAGICf = 12582912.0f;   // 1.5 * 2^23

    int g = blockIdx.x * 128 + threadIdx.x;
    int grp = g / 25088;                 // 0..7, uniform per block
    int q   = g % 25088;
    int w    = q % WW;
    int band = (q / WW) % 28;
    int b    = q / (WW * 28);
    int h0   = band * NS;
    int co_base = grp * NC;

    for (int i = threadIdx.x; i < NCP * NC * 10; i += 128) {
        int e  = i / 10;
        int k  = i % 10;
        int cp = e / NC;
        int lc = e % NC;
        int co = co_base + lc;
        float v0, v1;
        if (k < 9) {
            v0 = Wt[((2 * cp)     * COUT + co) * 9 + k];
            v1 = Wt[((2 * cp + 1) * COUT + co) * 9 + k];
        } else {
            v0 = bias[(2 * cp)     * COUT + co];
            v1 = bias[(2 * cp + 1) * COUT + co];
        }
        sW[i] = pk2(v0 * SCALEf, v1 * SCALEf);
    }
    __syncthreads();

    const f2 MAG2  = pk2(MAGICf,  MAGICf);
    const f2 NMAG2 = pk2(-MAGICf, -MAGICf);

    f2 acc[NC][NS];
#pragma unroll
    for (int c = 0; c < NC; ++c)
#pragma unroll
        for (int s = 0; s < NS; ++s) acc[c][s] = 0ULL;

    // Padded plane pointer for cp=0: rows h0..h0+5 cover outputs h0..h0+3.
    const f2* A = g_X + ((long)b * NCP * HP + h0) * WP + w;
    const long PSTRIDE = (long)HP * WP;

#pragma unroll 1
    for (int cp = 0; cp < NCP; ++cp) {
        // Prefetch next cp's 6 tap rows into L1 (~1 full compute block ahead).
        {
            const f2* An = (cp < NCP - 1) ? (A + PSTRIDE) : A;
#pragma unroll
            for (int r = 0; r < 6; ++r)
                pf_l1(An + r * WP);
        }

        // 6 rows x 3 cols of taps (coalesced LDG.64 in w).
        f2 tp[6][3];
#pragma unroll
        for (int r = 0; r < 6; ++r) {
#pragma unroll
            for (int k = 0; k < 3; ++k)
                tp[r][k] = A[r * WP + k];
        }
        A += PSTRIDE;

        const ulonglong2* wb =
            reinterpret_cast<const ulonglong2*>(&sW[cp * NC * 10]);

#pragma unroll
        for (int c = 0; c < NC; ++c) {
            ulonglong2 w01 = wb[c * 5 + 0];   // w0, w1
            ulonglong2 w23 = wb[c * 5 + 1];   // w2, w3
            ulonglong2 w45 = wb[c * 5 + 2];   // w4, w5
            ulonglong2 w67 = wb[c * 5 + 3];   // w6, w7
            ulonglong2 w8b = wb[c * 5 + 4];   // w8, bias

#pragma unroll
            for (int s = 0; s < NS; ++s) {
                f2 y = w8b.y;
                fma2i(y, tp[s][0],     w01.x);
                fma2i(y, tp[s][1],     w01.y);
                fma2i(y, tp[s][2],     w23.x);
                fma2i(y, tp[s + 1][0], w23.y);
                fma2i(y, tp[s + 1][1], w45.x);
                fma2i(y, tp[s + 1][2], w45.y);
                fma2i(y, tp[s + 2][0], w67.x);
                fma2i(y, tp[s + 2][1], w67.y);
                fma2i(y, tp[s + 2][2], w8b.x);

                add2i(y, MAG2);           // per-lane RNE -> integer
                add2i(y, NMAG2);
                add2i(acc[c][s], y);      // exact integer-valued sums
            }
        }
    }

    // Stores: scalar, coalesced in w. 16 stores (4 couts x 4 rows).
#pragma unroll
    for (int c = 0; c < NC; ++c) {
        int co = co_base + c;
        float* ob = out + ((long)(b * COUT + co) * HH + h0) * WW + w;
#pragma unroll
        for (int s = 0; s < NS; ++s)
            ob[s * WW] = lanesum(acc[c][s]) * INVf;
    }
}

extern "C" void kernel_launch(void* const* d_in, const int* in_sizes, int n_in,
                              void* d_out, int out_size)
{
    const float* x    = (const float*)d_in[0];   // [8,16,112,112]
    const float* Wt   = (const float*)d_in[1];   // [16,32,1,3,3]
    const float* bias = (const float*)d_in[2];   // [16,32]
    float* out        = (float*)d_out;           // [8,32,112,112]

    // NB*NCP*HP*PPW = 415872 -> 1625 blocks of 256 (guarded).
    prepass_kernel<<<1625, 256>>>(x);
    // 200704 threads = 1568 blocks * 128.
    demolition_conv2d_kernel<<<1568, 128>>>(Wt, bias, out);
}